// round 13
// baseline (speedup 1.0000x reference)
#include <cuda_runtime.h>
#include <cuda_bf16.h>
#include <math.h>

#define FNUM  32
#define BATCH 2048
#define KD    64
#define HD    64
#define WROW  72     // Wt row stride (bf16)
#define NHC   64     // half-chunks (8 pair-rows each); 32 MMA chunks

__device__ __forceinline__ unsigned cvt_bf16x2(float hi, float lo) {
    unsigned r;
    asm("cvt.rn.bf16x2.f32 %0, %1, %2;" : "=r"(r) : "f"(hi), "f"(lo));
    return r;
}

__device__ __forceinline__ unsigned hmul2u(unsigned a, unsigned b) {
    unsigned r;
    asm("mul.rn.bf16x2 %0, %1, %2;" : "=r"(r) : "r"(a), "r"(b));
    return r;
}

__device__ __forceinline__ void mma16816(float* c, const unsigned* a, unsigned b0, unsigned b1) {
    asm volatile("mma.sync.aligned.m16n8k16.row.col.f32.bf16.bf16.f32 "
                 "{%0,%1,%2,%3}, {%4,%5,%6,%7}, {%8,%9}, {%0,%1,%2,%3};"
                 : "+f"(c[0]), "+f"(c[1]), "+f"(c[2]), "+f"(c[3])
                 : "r"(a[0]), "r"(a[1]), "r"(a[2]), "r"(a[3]), "r"(b0), "r"(b1));
}

// ---- compile-time pair schedule: 64 half-chunks of 8 rows, each sharing one field ----
// Full 8-groups along i (48), leftovers regrouped along j (16, 16 pad slots of 512).
struct Sched {
    unsigned char fs[NHC];        // shared field of the half-chunk
    unsigned char fp[NHC][8];     // partner field per row; 0xFF = pad
};
static constexpr Sched make_sched() {
    Sched s{};
    int h = 0;
    for (int i = 0; i < 31; i++) {                      // full i-groups
        int nfull = (31 - i) / 8;
        for (int g = 0; g < nfull; g++) {
            s.fs[h] = (unsigned char)i;
            for (int r = 0; r < 8; r++) s.fp[h][r] = (unsigned char)(i + 1 + 8 * g + r);
            h++;
        }
    }
    for (int j = 31; j >= 1; j--) {                     // leftovers grouped by j
        int buf[32] = {};
        int n = 0;
        for (int i = 0; i < j; i++) {
            int start_left = i + 1 + 8 * ((31 - i) / 8);
            if (j >= start_left) buf[n++] = i;
        }
        for (int g = 0; g < n; g += 8) {
            s.fs[h] = (unsigned char)j;
            for (int r = 0; r < 8; r++)
                s.fp[h][r] = (unsigned char)((g + r < n) ? buf[g + r] : 0xFF);
            h++;
        }
    }
    while (h < NHC) { s.fs[h] = 0; for (int r = 0; r < 8; r++) s.fp[h][r] = 0xFF; h++; }
    return s;
}
__constant__ Sched dsched = make_sched();

// physical placement of logical bf16x2-pair m (=k/2, 0..31):
//   kc=m>>3, r=m&7, q=r&3, hi=r>>2  ->  phys uint index q*8 + kc*2 + hi
// 16B segments XOR-swizzled by (field & 7).
__device__ __forceinline__ int vperm_idx(int m, int f) {
    int kc = m >> 3, r = m & 7, q = r & 3, hi = r >> 2;
    int pu = q * 8 + kc * 2 + hi;
    return ((((pu >> 2) ^ (f & 7)) << 2)) | (pu & 3);
}

__global__ void __launch_bounds__(128)
afm_kernel(const int* __restrict__ x, const float* __restrict__ emb,
           const float* __restrict__ at_w, const float* __restrict__ at_b,
           const float* __restrict__ at_h, const float* __restrict__ pvec,
           const float* __restrict__ w0, const float* __restrict__ w1,
           float* __restrict__ out)
{
    __shared__ __align__(16) unsigned       Vb[2][FNUM][32];   // bf16x2, permuted+swizzled
    __shared__ __align__(16) __nv_bfloat16  Wt[HD][WROW];      // Wt[n][k] = at_w[k][n]
    __shared__ float2          bhsh[HD];     // {at_b[h], at_h[h]}
    __shared__ float           psh[KD];
    __shared__ unsigned char   fssh[NHC];
    __shared__ unsigned char   fpsh[NHC][8];
    __shared__ float           warpsum[2][4];
    __shared__ float           fm1sh[2];
    __shared__ int             xsh[2][FNUM];

    const int tid = threadIdx.x;
    const int b0  = blockIdx.x * 2;

    // --- fm1 + stage x indices, 2 batches ---
    if (tid < 64) {
        int bb = tid >> 5, f = tid & 31;
        int xv = x[f * BATCH + b0 + bb];
        xsh[bb][f] = xv;
        float v = w1[xv];
        #pragma unroll
        for (int o = 16; o; o >>= 1) v += __shfl_xor_sync(0xffffffffu, v, o);
        if (f == 0) fm1sh[bb] = v;
    }
    if (tid < HD) {
        bhsh[tid] = make_float2(at_b[tid], at_h[tid]);
        psh[tid]  = pvec[tid];
    }
    if (tid < NHC) fssh[tid] = dsched.fs[tid];
    for (int t = tid; t < NHC * 8; t += 128)
        ((unsigned char*)fpsh)[t] = ((const unsigned char*)dsched.fp)[t];
    __syncthreads();   // xsh visible

    // --- load V rows (fp32 gmem -> bf16x2 permuted smem), 64 rows, 2 threads/row ---
    {
        int row = tid >> 1, half = tid & 1;     // half: logical k 0..31 / 32..63
        int bb = row >> 5, f = row & 31;
        const float4* src = reinterpret_cast<const float4*>(emb + (size_t)xsh[bb][f] * KD) + half * 8;
        unsigned* dst = Vb[bb][f];
        #pragma unroll
        for (int u = 0; u < 8; u++) {
            float4 v4 = src[u];
            int m = half * 16 + 2 * u;
            dst[vperm_idx(m, f)]     = cvt_bf16x2(v4.y, v4.x);
            dst[vperm_idx(m + 1, f)] = cvt_bf16x2(v4.w, v4.z);
        }
    }
    // --- load W^T ---
    for (int idx = tid; idx < HD * KD; idx += 128) {
        int n = idx >> 6, k = idx & 63;
        Wt[n][k] = __float2bfloat16(at_w[k * HD + n]);
    }
    __syncthreads();

    const int lane = tid & 31;
    const int warp = tid >> 5;
    const int quad = lane >> 2;          // fragment row group (0..7)
    const int q    = lane & 3;           // fragment k/n sub-lane

    // per-thread (bias, at_h) for owned C columns: n = nt*8 + 2q + {0,1}
    float2 bh0[8], bh1[8];
    #pragma unroll
    for (int nt = 0; nt < 8; nt++) {
        int cb = nt * 8 + q * 2;
        bh0[nt] = bhsh[cb];
        bh1[nt] = bhsh[cb + 1];
    }

    // --- build all B fragments once by plain loads (logical k-order) ---
    unsigned Bf[8][8];
    #pragma unroll
    for (int nt = 0; nt < 8; nt++) {
        const __nv_bfloat16* wr = Wt[nt * 8 + quad];
        #pragma unroll
        for (int kc = 0; kc < 4; kc++) {
            Bf[nt][2 * kc]     = *reinterpret_cast<const unsigned*>(wr + 16 * kc + 2 * q);
            Bf[nt][2 * kc + 1] = *reinterpret_cast<const unsigned*>(wr + 16 * kc + 2 * q + 8);
        }
    }
    // --- p-vector B fragment (column 0 only: quad 0 lanes carry p, rest zero) ---
    unsigned pc0[4], pc1[4];
    #pragma unroll
    for (int kc = 0; kc < 4; kc++) {
        if (quad == 0) {
            pc0[kc] = cvt_bf16x2(psh[16 * kc + 2 * q + 1], psh[16 * kc + 2 * q]);
            pc1[kc] = cvt_bf16x2(psh[16 * kc + 2 * q + 9], psh[16 * kc + 2 * q + 8]);
        } else { pc0[kc] = 0u; pc1[kc] = 0u; }
    }

    for (int bb = 0; bb < 2; bb++) {
        float att = 0.0f;

        for (int c = warp; c < 32; c += 4) {       // exactly 8 chunks per warp
            int hA = 2 * c, hB = hA + 1;
            int fsA = fssh[hA], fsB = fssh[hB];
            int fpA = fpsh[hA][quad], fpB = fpsh[hB][quad];
            float mA = 1.0f, mB = 1.0f;
            if (fpA == 255) { fpA = fsA; mA = 0.0f; }
            if (fpB == 255) { fpB = fsB; mB = 0.0f; }

            const uint4* RsA = reinterpret_cast<const uint4*>(Vb[bb][fsA]);
            const uint4* RpA = reinterpret_cast<const uint4*>(Vb[bb][fpA]);
            const uint4* RsB = reinterpret_cast<const uint4*>(Vb[bb][fsB]);
            const uint4* RpB = reinterpret_cast<const uint4*>(Vb[bb][fpB]);
            int s0 = 2 * q, s1 = s0 + 1;
            uint4 i0a = RsA[s0 ^ (fsA & 7)], i0b = RsA[s1 ^ (fsA & 7)];  // broadcast across quads
            uint4 j0a = RpA[s0 ^ (fpA & 7)], j0b = RpA[s1 ^ (fpA & 7)];
            uint4 i1a = RsB[s0 ^ (fsB & 7)], i1b = RsB[s1 ^ (fsB & 7)];  // broadcast across quads
            uint4 j1a = RpB[s0 ^ (fpB & 7)], j1b = RpB[s1 ^ (fpB & 7)];

            // A fragments: VV in bf16 via packed multiplies
            unsigned A[4][4];
            A[0][0] = hmul2u(i0a.x, j0a.x);  A[0][2] = hmul2u(i0a.y, j0a.y);
            A[1][0] = hmul2u(i0a.z, j0a.z);  A[1][2] = hmul2u(i0a.w, j0a.w);
            A[2][0] = hmul2u(i0b.x, j0b.x);  A[2][2] = hmul2u(i0b.y, j0b.y);
            A[3][0] = hmul2u(i0b.z, j0b.z);  A[3][2] = hmul2u(i0b.w, j0b.w);
            A[0][1] = hmul2u(i1a.x, j1a.x);  A[0][3] = hmul2u(i1a.y, j1a.y);
            A[1][1] = hmul2u(i1a.z, j1a.z);  A[1][3] = hmul2u(i1a.w, j1a.w);
            A[2][1] = hmul2u(i1b.x, j1b.x);  A[2][3] = hmul2u(i1b.y, j1b.y);
            A[3][1] = hmul2u(i1b.z, j1b.z);  A[3][3] = hmul2u(i1b.w, j1b.w);

            // g = VV . p via MMA into column 0
            float accg[4] = {0.f, 0.f, 0.f, 0.f};
            mma16816(accg, A[0], pc0[0], pc1[0]);
            mma16816(accg, A[1], pc0[1], pc1[1]);
            mma16816(accg, A[2], pc0[2], pc1[2]);
            mma16816(accg, A[3], pc0[3], pc1[3]);

            // hid GEMM with fused per-nt epilogue
            float slo = 0.0f, shi = 0.0f;
            #pragma unroll
            for (int nt = 0; nt < 8; nt += 2) {
                float acc0[4] = {0.f, 0.f, 0.f, 0.f};
                float acc1[4] = {0.f, 0.f, 0.f, 0.f};
                mma16816(acc0, A[0], Bf[nt][0], Bf[nt][1]);
                mma16816(acc0, A[1], Bf[nt][2], Bf[nt][3]);
                mma16816(acc0, A[2], Bf[nt][4], Bf[nt][5]);
                mma16816(acc0, A[3], Bf[nt][6], Bf[nt][7]);
                mma16816(acc1, A[0], Bf[nt + 1][0], Bf[nt + 1][1]);
                mma16816(acc1, A[1], Bf[nt + 1][2], Bf[nt + 1][3]);
                mma16816(acc1, A[2], Bf[nt + 1][4], Bf[nt + 1][5]);
                mma16816(acc1, A[3], Bf[nt + 1][6], Bf[nt + 1][7]);
                slo += fmaxf(acc0[0] + bh0[nt].x,     0.0f) * bh0[nt].y
                     + fmaxf(acc0[1] + bh1[nt].x,     0.0f) * bh1[nt].y
                     + fmaxf(acc1[0] + bh0[nt + 1].x, 0.0f) * bh0[nt + 1].y
                     + fmaxf(acc1[1] + bh1[nt + 1].x, 0.0f) * bh1[nt + 1].y;
                shi += fmaxf(acc0[2] + bh0[nt].x,     0.0f) * bh0[nt].y
                     + fmaxf(acc0[3] + bh1[nt].x,     0.0f) * bh1[nt].y
                     + fmaxf(acc1[2] + bh0[nt + 1].x, 0.0f) * bh0[nt + 1].y
                     + fmaxf(acc1[3] + bh1[nt + 1].x, 0.0f) * bh1[nt + 1].y;
            }

            // reduce score over the 4 n-sublanes; g complete at q==0; mask pads
            slo += __shfl_xor_sync(0xffffffffu, slo, 1);
            slo += __shfl_xor_sync(0xffffffffu, slo, 2);
            shi += __shfl_xor_sync(0xffffffffu, shi, 1);
            shi += __shfl_xor_sync(0xffffffffu, shi, 2);
            if (q == 0) att += slo * (accg[0] * mA) + shi * (accg[2] * mB);
        }

        #pragma unroll
        for (int o = 16; o; o >>= 1) att += __shfl_xor_sync(0xffffffffu, att, o);
        if (lane == 0) warpsum[bb][warp] = att;
    }

    __syncthreads();
    if (tid < 2) {
        float logit = warpsum[tid][0] + warpsum[tid][1] + warpsum[tid][2] + warpsum[tid][3]
                    + fm1sh[tid] + w0[0];
        out[b0 + tid] = 1.0f / (1.0f + expf(-logit));
    }
}

extern "C" void kernel_launch(void* const* d_in, const int* in_sizes, int n_in,
                              void* d_out, int out_size) {
    const int*   x    = (const int*)d_in[0];
    const float* emb  = (const float*)d_in[1];
    const float* at_w = (const float*)d_in[2];
    const float* at_b = (const float*)d_in[3];
    const float* at_h = (const float*)d_in[4];
    const float* pvec = (const float*)d_in[5];
    const float* w0   = (const float*)d_in[6];
    const float* w1   = (const float*)d_in[7];
    float* out = (float*)d_out;
    afm_kernel<<<BATCH / 2, 128>>>(x, emb, at_w, at_b, at_h, pvec, w0, w1, out);
}